// round 1
// baseline (speedup 1.0000x reference)
#include <cuda_runtime.h>
#include <cuda_bf16.h>

#define N_NODES 50000
#define N_EDGES 800000
#define D 128
#define N_CLS 47
#define N_CLS_PAD 48

// ---------------- scratch (no allocations allowed) ----------------
__device__ int   g_deg[N_NODES];
__device__ int   g_row_ptr[N_NODES + 1];
__device__ int   g_cursor[N_NODES];
__device__ int   g_csr_src[N_EDGES];
__device__ float g_inv_deg[N_NODES];
__device__ float g_h1[N_NODES * D];
__device__ float g_h2[N_NODES * D];
__device__ float g_agg[N_NODES * D];
__device__ float g_ws2p[D * N_CLS_PAD];
__device__ float g_wn2p[D * N_CLS_PAD];
__device__ float g_b2p[N_CLS_PAD];

// ---------------- CSR build ----------------
__global__ void zero_deg_kernel() {
    int i = blockIdx.x * blockDim.x + threadIdx.x;
    if (i < N_NODES) g_deg[i] = 0;
}

__global__ void count_deg_kernel(const int* __restrict__ dst) {
    int e = blockIdx.x * blockDim.x + threadIdx.x;
    if (e < N_EDGES) atomicAdd(&g_deg[dst[e]], 1);
}

// Single-block exclusive scan over 50000 degrees -> row_ptr, cursor, inv_deg.
__global__ void scan_kernel() {
    __shared__ int ssum[1024];
    int tid = threadIdx.x;
    const int CH = (N_NODES + 1023) / 1024;  // 49
    int start = tid * CH;
    int end = start + CH;
    if (end > N_NODES) end = N_NODES;
    int s = 0;
    for (int i = start; i < end; i++) s += g_deg[i];
    ssum[tid] = s;
    __syncthreads();
    // Hillis-Steele inclusive scan
    for (int off = 1; off < 1024; off <<= 1) {
        int v = (tid >= off) ? ssum[tid - off] : 0;
        __syncthreads();
        ssum[tid] += v;
        __syncthreads();
    }
    int run = ssum[tid] - s;  // exclusive prefix
    for (int i = start; i < end; i++) {
        g_row_ptr[i] = run;
        g_cursor[i] = run;
        int d = g_deg[i];
        g_inv_deg[i] = 1.0f / (float)(d > 1 ? d : 1);
        run += d;
    }
    if (tid == 1023) g_row_ptr[N_NODES] = N_EDGES;
}

__global__ void fill_csr_kernel(const int* __restrict__ src, const int* __restrict__ dst) {
    int e = blockIdx.x * blockDim.x + threadIdx.x;
    if (e < N_EDGES) {
        int idx = atomicAdd(&g_cursor[dst[e]], 1);
        g_csr_src[idx] = src[e];
    }
}

// ---------------- pad layer-2 weights 47 -> 48 cols ----------------
__global__ void pad_w2_kernel(const float* __restrict__ Ws2, const float* __restrict__ Wn2,
                              const float* __restrict__ b2) {
    int i = blockIdx.x * blockDim.x + threadIdx.x;
    if (i < D * N_CLS_PAD) {
        int r = i / N_CLS_PAD, c = i % N_CLS_PAD;
        g_ws2p[i] = (c < N_CLS) ? Ws2[r * N_CLS + c] : 0.0f;
        g_wn2p[i] = (c < N_CLS) ? Wn2[r * N_CLS + c] : 0.0f;
        if (i < N_CLS_PAD) g_b2p[i] = (i < N_CLS) ? b2[i] : 0.0f;
    }
}

// ---------------- mean aggregation: one warp per node, gather over CSR ----------------
__global__ void agg_kernel(const float* __restrict__ h) {
    int warp = (blockIdx.x * blockDim.x + threadIdx.x) >> 5;
    int lane = threadIdx.x & 31;
    if (warp >= N_NODES) return;
    int beg = g_row_ptr[warp];
    int end = g_row_ptr[warp + 1];
    const float4* __restrict__ h4 = (const float4*)h;
    float4 acc = make_float4(0.f, 0.f, 0.f, 0.f);
    for (int e = beg; e < end; e++) {
        int u = __ldg(&g_csr_src[e]);
        float4 v = __ldg(&h4[(long)u * 32 + lane]);
        acc.x += v.x; acc.y += v.y; acc.z += v.z; acc.w += v.w;
    }
    float s = g_inv_deg[warp];
    acc.x *= s; acc.y *= s; acc.z *= s; acc.w *= s;
    ((float4*)g_agg)[(long)warp * 32 + lane] = acc;
}

// ---------------- fused dual GEMM: out = h@Ws + agg@Wn + b (+relu) ----------------
// Thread layout: CG column-groups (4 cols each) x RG row-groups; RPT rows per thread.
template <int CG, int RG, int RPT>
__global__ void gemm_kernel(const float* __restrict__ hin,
                            const float* __restrict__ Ws, const float* __restrict__ Wn,
                            const float* __restrict__ bias, float* __restrict__ out,
                            int nout_pad, int nout_real, int relu) {
    constexpr int TR = RG * RPT;          // rows per block
    constexpr int NT = CG * RG;           // threads per block
    __shared__ float sh_h[TR][D];
    __shared__ float sh_a[TR][D];
    int tid = threadIdx.x;
    int m0 = blockIdx.x * TR;

    const float4* __restrict__ h4 = (const float4*)hin;
    const float4* __restrict__ a4 = (const float4*)g_agg;
    for (int i = tid; i < TR * (D / 4); i += NT) {
        int r = i >> 5;      // D/4 = 32
        int c = i & 31;
        int m = m0 + r;
        float4 hv = make_float4(0.f, 0.f, 0.f, 0.f);
        float4 av = make_float4(0.f, 0.f, 0.f, 0.f);
        if (m < N_NODES) {
            hv = h4[(long)m * 32 + c];
            av = a4[(long)m * 32 + c];
        }
        ((float4*)&sh_h[r][0])[c] = hv;
        ((float4*)&sh_a[r][0])[c] = av;
    }
    __syncthreads();

    int cg = tid % CG;
    int rg = tid / CG;
    int n0 = cg * 4;

    float acc[RPT][4];
#pragma unroll
    for (int r = 0; r < RPT; r++)
#pragma unroll
        for (int j = 0; j < 4; j++) acc[r][j] = 0.0f;

#pragma unroll 4
    for (int k = 0; k < D; k++) {
        float4 ws = *(const float4*)&Ws[k * nout_pad + n0];
        float4 wn = *(const float4*)&Wn[k * nout_pad + n0];
#pragma unroll
        for (int r = 0; r < RPT; r++) {
            int row = rg * RPT + r;
            float hv = sh_h[row][k];
            float av = sh_a[row][k];
            acc[r][0] = fmaf(hv, ws.x, fmaf(av, wn.x, acc[r][0]));
            acc[r][1] = fmaf(hv, ws.y, fmaf(av, wn.y, acc[r][1]));
            acc[r][2] = fmaf(hv, ws.z, fmaf(av, wn.z, acc[r][2]));
            acc[r][3] = fmaf(hv, ws.w, fmaf(av, wn.w, acc[r][3]));
        }
    }

    float4 bb = *(const float4*)&bias[n0];
    float bv[4] = {bb.x, bb.y, bb.z, bb.w};
#pragma unroll
    for (int r = 0; r < RPT; r++) {
        int m = m0 + rg * RPT + r;
        if (m >= N_NODES) continue;
#pragma unroll
        for (int j = 0; j < 4; j++) {
            int n = n0 + j;
            if (n < nout_real) {
                float v = acc[r][j] + bv[j];
                if (relu) v = fmaxf(v, 0.0f);
                out[(long)m * nout_real + n] = v;
            }
        }
    }
}

// ---------------- launch ----------------
extern "C" void kernel_launch(void* const* d_in, const int* in_sizes, int n_in,
                              void* d_out, int out_size) {
    const float* features = (const float*)d_in[0];
    const int*   src      = (const int*)d_in[1];
    const int*   dst      = (const int*)d_in[2];
    const float* Ws0 = (const float*)d_in[3];
    const float* Wn0 = (const float*)d_in[4];
    const float* b0  = (const float*)d_in[5];
    const float* Ws1 = (const float*)d_in[6];
    const float* Wn1 = (const float*)d_in[7];
    const float* b1  = (const float*)d_in[8];
    const float* Ws2 = (const float*)d_in[9];
    const float* Wn2 = (const float*)d_in[10];
    const float* b2  = (const float*)d_in[11];
    float* out = (float*)d_out;

    void* p;
    cudaGetSymbolAddress(&p, g_h1);   float* h1   = (float*)p;
    cudaGetSymbolAddress(&p, g_h2);   float* h2   = (float*)p;
    cudaGetSymbolAddress(&p, g_ws2p); float* ws2p = (float*)p;
    cudaGetSymbolAddress(&p, g_wn2p); float* wn2p = (float*)p;
    cudaGetSymbolAddress(&p, g_b2p);  float* b2p  = (float*)p;

    // CSR build (per launch; deterministic up to atomic ordering of equal-valued sums)
    zero_deg_kernel<<<(N_NODES + 255) / 256, 256>>>();
    count_deg_kernel<<<(N_EDGES + 255) / 256, 256>>>(dst);
    scan_kernel<<<1, 1024>>>();
    fill_csr_kernel<<<(N_EDGES + 255) / 256, 256>>>(src, dst);
    pad_w2_kernel<<<(D * N_CLS_PAD + 255) / 256, 256>>>(Ws2, Wn2, b2);

    const int AGG_BLOCKS = (N_NODES * 32 + 255) / 256;

    // Layer 0: relu(features@Ws0 + agg(features)@Wn0 + b0)
    agg_kernel<<<AGG_BLOCKS, 256>>>(features);
    gemm_kernel<32, 4, 8><<<(N_NODES + 31) / 32, 128>>>(features, Ws0, Wn0, b0, h1, D, D, 1);

    // Layer 1
    agg_kernel<<<AGG_BLOCKS, 256>>>(h1);
    gemm_kernel<32, 4, 8><<<(N_NODES + 31) / 32, 128>>>(h1, Ws1, Wn1, b1, h2, D, D, 1);

    // Layer 2 (47 classes, padded weights to 48, no relu)
    agg_kernel<<<AGG_BLOCKS, 256>>>(h2);
    gemm_kernel<12, 8, 4><<<(N_NODES + 31) / 32, 96>>>(h2, ws2p, wn2p, b2p, out, N_CLS_PAD, N_CLS, 0);
}

// round 3
// speedup vs baseline: 1.2237x; 1.2237x over previous
#include <cuda_runtime.h>
#include <cuda_bf16.h>
#include <cstdint>

#define N_NODES 50000
#define N_EDGES 800000
#define D 128
#define N_CLS 47

// ---------------- scratch (no allocations allowed) ----------------
__device__ int   g_deg[N_NODES];
__device__ int   g_row_ptr[N_NODES + 1];
__device__ int   g_cursor[N_NODES];
__device__ int   g_csr_src[N_EDGES];
__device__ float g_inv_deg[N_NODES];

__device__ float g_h1[N_NODES * D];
__device__ float g_h2[N_NODES * D];

__device__ __nv_bfloat16 g_f_hi[N_NODES * D];
__device__ __nv_bfloat16 g_f_lo[N_NODES * D];
__device__ __nv_bfloat16 g_h1_hi[N_NODES * D];
__device__ __nv_bfloat16 g_h1_lo[N_NODES * D];
__device__ __nv_bfloat16 g_h2_hi[N_NODES * D];
__device__ __nv_bfloat16 g_h2_lo[N_NODES * D];
__device__ __nv_bfloat16 g_agg_hi[N_NODES * D];
__device__ __nv_bfloat16 g_agg_lo[N_NODES * D];

// Weights pre-transposed + K-concatenated: B[n][k], k in [0,256)
__device__ __nv_bfloat16 g_B0hi[128 * 256];
__device__ __nv_bfloat16 g_B0lo[128 * 256];
__device__ __nv_bfloat16 g_B1hi[128 * 256];
__device__ __nv_bfloat16 g_B1lo[128 * 256];
__device__ __nv_bfloat16 g_B2hi[48 * 256];
__device__ __nv_bfloat16 g_B2lo[48 * 256];

// ---------------- PTX helpers (all baseline PTX, no sm_103a-only features) ----------------
__device__ __forceinline__ uint32_t s2u(const void* p) {
    uint32_t a;
    asm("{ .reg .u64 t; cvta.to.shared.u64 t, %1; cvt.u32.u64 %0, t; }" : "=r"(a) : "l"(p));
    return a;
}

__device__ __forceinline__ void ldsm_x4(uint32_t& r0, uint32_t& r1, uint32_t& r2, uint32_t& r3,
                                        uint32_t addr) {
    asm volatile("ldmatrix.sync.aligned.m8n8.x4.shared.b16 {%0,%1,%2,%3}, [%4];"
                 : "=r"(r0), "=r"(r1), "=r"(r2), "=r"(r3) : "r"(addr));
}

__device__ __forceinline__ void ldsm_x2(uint32_t& r0, uint32_t& r1, uint32_t addr) {
    asm volatile("ldmatrix.sync.aligned.m8n8.x2.shared.b16 {%0,%1}, [%2];"
                 : "=r"(r0), "=r"(r1) : "r"(addr));
}

__device__ __forceinline__ void mma_bf16(float* c, const uint32_t* a, const uint32_t* b) {
    asm volatile(
        "mma.sync.aligned.m16n8k16.row.col.f32.bf16.bf16.f32 "
        "{%0,%1,%2,%3}, {%4,%5,%6,%7}, {%8,%9}, {%0,%1,%2,%3};"
        : "+f"(c[0]), "+f"(c[1]), "+f"(c[2]), "+f"(c[3])
        : "r"(a[0]), "r"(a[1]), "r"(a[2]), "r"(a[3]), "r"(b[0]), "r"(b[1]));
}

// ---------------- CSR build ----------------
__global__ void zero_deg_kernel() {
    int i = blockIdx.x * blockDim.x + threadIdx.x;
    if (i < N_NODES) g_deg[i] = 0;
}

__global__ void count_deg_kernel(const int* __restrict__ dst) {
    int e = blockIdx.x * blockDim.x + threadIdx.x;
    if (e < N_EDGES) atomicAdd(&g_deg[dst[e]], 1);
}

__global__ void scan_kernel() {
    __shared__ int ssum[1024];
    int tid = threadIdx.x;
    const int CH = (N_NODES + 1023) / 1024;
    int start = tid * CH;
    int end = start + CH;
    if (end > N_NODES) end = N_NODES;
    int s = 0;
    for (int i = start; i < end; i++) s += g_deg[i];
    ssum[tid] = s;
    __syncthreads();
    for (int off = 1; off < 1024; off <<= 1) {
        int v = (tid >= off) ? ssum[tid - off] : 0;
        __syncthreads();
        ssum[tid] += v;
        __syncthreads();
    }
    int run = ssum[tid] - s;
    for (int i = start; i < end; i++) {
        g_row_ptr[i] = run;
        g_cursor[i] = run;
        int d = g_deg[i];
        g_inv_deg[i] = 1.0f / (float)(d > 1 ? d : 1);
        run += d;
    }
    if (tid == 1023) g_row_ptr[N_NODES] = N_EDGES;
}

__global__ void fill_csr_kernel(const int* __restrict__ src, const int* __restrict__ dst) {
    int e = blockIdx.x * blockDim.x + threadIdx.x;
    if (e < N_EDGES) {
        int idx = atomicAdd(&g_cursor[dst[e]], 1);
        g_csr_src[idx] = src[e];
    }
}

// ---------------- weight prep: B[n][k] = concat_k(Ws, Wn)[k][n], bf16 hi/lo split ----------------
__global__ void prep_B_kernel(const float* __restrict__ Ws, const float* __restrict__ Wn,
                              int nreal, int npad,
                              __nv_bfloat16* __restrict__ Bh, __nv_bfloat16* __restrict__ Bl) {
    int i = blockIdx.x * blockDim.x + threadIdx.x;
    if (i >= npad * 256) return;
    int n = i / 256, k = i % 256;
    float w = 0.0f;
    if (n < nreal) w = (k < 128) ? Ws[k * nreal + n] : Wn[(k - 128) * nreal + n];
    __nv_bfloat16 hi = __float2bfloat16(w);
    float rem = w - __bfloat162float(hi);
    Bh[i] = hi;
    Bl[i] = __float2bfloat16(rem);
}

// ---------------- fp32 -> bf16 hi/lo split (features only) ----------------
__global__ void split_kernel(const float* __restrict__ x,
                             __nv_bfloat16* __restrict__ hi, __nv_bfloat16* __restrict__ lo,
                             int n) {
    int i = blockIdx.x * blockDim.x + threadIdx.x;
    if (i >= n) return;
    float v = x[i];
    __nv_bfloat16 h = __float2bfloat16(v);
    hi[i] = h;
    lo[i] = __float2bfloat16(v - __bfloat162float(h));
}

// ---------------- mean aggregation: one warp per node, writes bf16 hi/lo ----------------
__global__ void agg_kernel(const float* __restrict__ h) {
    int warp = (blockIdx.x * blockDim.x + threadIdx.x) >> 5;
    int lane = threadIdx.x & 31;
    if (warp >= N_NODES) return;
    int beg = g_row_ptr[warp];
    int end = g_row_ptr[warp + 1];
    const float4* __restrict__ h4 = (const float4*)h;
    float4 acc = make_float4(0.f, 0.f, 0.f, 0.f);
    for (int e = beg; e < end; e++) {
        int u = __ldg(&g_csr_src[e]);
        float4 v = __ldg(&h4[(long)u * 32 + lane]);
        acc.x += v.x; acc.y += v.y; acc.z += v.z; acc.w += v.w;
    }
    float s = g_inv_deg[warp];
    float vals[4] = {acc.x * s, acc.y * s, acc.z * s, acc.w * s};
    unsigned short hs[4], ls[4];
#pragma unroll
    for (int j = 0; j < 4; j++) {
        __nv_bfloat16 hv = __float2bfloat16(vals[j]);
        hs[j] = __bfloat16_as_ushort(hv);
        ls[j] = __bfloat16_as_ushort(__float2bfloat16(vals[j] - __bfloat162float(hv)));
    }
    long off = (long)warp * 128 + lane * 4;
    *(ushort4*)&g_agg_hi[off] = make_ushort4(hs[0], hs[1], hs[2], hs[3]);
    *(ushort4*)&g_agg_lo[off] = make_ushort4(ls[0], ls[1], ls[2], ls[3]);
}

// ---------------- HMMA fused GEMM: D[128,NOUT] = [x|agg](hi+lo) @ B(hi+lo)^T + b ----------------
// Error-split: acc = a_hi*b_hi + a_hi*b_lo + a_lo*b_hi  (drops lo*lo, ~2^-16 relative)
template <int NOUT, bool RELU, bool SPLIT>
__global__ void __launch_bounds__(256, 1) gemm_mma(
    const __nv_bfloat16* __restrict__ x_hi, const __nv_bfloat16* __restrict__ x_lo,
    const __nv_bfloat16* __restrict__ Bhi_g, const __nv_bfloat16* __restrict__ Blo_g,
    const float* __restrict__ bias, int nbias,
    float* __restrict__ out, int ostride,
    __nv_bfloat16* __restrict__ o_hi, __nv_bfloat16* __restrict__ o_lo) {
    constexpr int KS_B = 264;   // bf16 row stride for B smem (256 + 8 pad -> conflict-free ldsm)
    constexpr int KS_A = 136;   // bf16 row stride for A smem chunk (128 + 8 pad)
    constexpr int MT = (NOUT == 128) ? 2 : 1;   // m16 tiles per warp
    constexpr int NT = (NOUT == 128) ? 8 : 6;   // n8 tiles per warp

    extern __shared__ __nv_bfloat16 sm[];
    __nv_bfloat16* sBhi = sm;
    __nv_bfloat16* sBlo = sBhi + NOUT * KS_B;
    __nv_bfloat16* sAhi = sBlo + NOUT * KS_B;
    __nv_bfloat16* sAlo = sAhi + 128 * KS_A;
    float* sbias = (float*)(sAlo + 128 * KS_A);

    int tid = threadIdx.x;
    int wid = tid >> 5;
    int lane = tid & 31;
    int m0 = blockIdx.x * 128;

    int warpM = (NOUT == 128) ? (wid & 3) * 32 : wid * 16;
    int warpN = (NOUT == 128) ? (wid >> 2) * 64 : 0;

    // ---- load B (resident, full K=256, hi+lo) ----
    for (int i = tid; i < NOUT * 32; i += 256) {
        int n = i >> 5;
        int k8 = (i & 31) << 3;
        *(uint4*)&sBhi[n * KS_B + k8] = *(const uint4*)&Bhi_g[n * 256 + k8];
        *(uint4*)&sBlo[n * KS_B + k8] = *(const uint4*)&Blo_g[n * 256 + k8];
    }
    if (tid < NOUT) sbias[tid] = (tid < nbias) ? bias[tid] : 0.0f;

    float acc[MT][NT][4];
#pragma unroll
    for (int mt = 0; mt < MT; mt++)
#pragma unroll
        for (int nt = 0; nt < NT; nt++)
#pragma unroll
            for (int j = 0; j < 4; j++) acc[mt][nt][j] = 0.0f;

    uint32_t uAhi = s2u(sAhi), uAlo = s2u(sAlo);
    uint32_t uBhi = s2u(sBhi), uBlo = s2u(sBlo);

    // ldmatrix per-lane address components
    int g = lane >> 3;                        // 0..3
    int rA = (g & 1) * 8 + (lane & 7);        // A row within 16
    int kA = (g >> 1) * 8;                    // A k offset within 16
    int rB = lane & 7;                        // B n-row within 8
    int kB = ((lane >> 3) & 1) * 8;           // B k offset within 16

    // ---- two K-chunks: chunk 0 = x (self), chunk 1 = agg (neighbors) ----
#pragma unroll 1
    for (int c = 0; c < 2; c++) {
        const __nv_bfloat16* shi = (c == 0) ? x_hi : g_agg_hi;
        const __nv_bfloat16* slo = (c == 0) ? x_lo : g_agg_lo;
        __syncthreads();
        for (int i = tid; i < 128 * 16; i += 256) {
            int r = i >> 4;
            int k8 = (i & 15) << 3;
            int m = m0 + r;
            uint4 vh = make_uint4(0, 0, 0, 0), vl = make_uint4(0, 0, 0, 0);
            if (m < N_NODES) {
                vh = *(const uint4*)&shi[(long)m * 128 + k8];
                vl = *(const uint4*)&slo[(long)m * 128 + k8];
            }
            *(uint4*)&sAhi[r * KS_A + k8] = vh;
            *(uint4*)&sAlo[r * KS_A + k8] = vl;
        }
        __syncthreads();

#pragma unroll
        for (int kk = 0; kk < 128; kk += 16) {
            uint32_t ah[MT][4], al[MT][4];
#pragma unroll
            for (int mt = 0; mt < MT; mt++) {
                uint32_t off = (uint32_t)((warpM + mt * 16 + rA) * KS_A + kk + kA) * 2;
                ldsm_x4(ah[mt][0], ah[mt][1], ah[mt][2], ah[mt][3], uAhi + off);
                ldsm_x4(al[mt][0], al[mt][1], al[mt][2], al[mt][3], uAlo + off);
            }
            uint32_t bh[NT][2], bl[NT][2];
#pragma unroll
            for (int nt = 0; nt < NT; nt++) {
                uint32_t off = (uint32_t)((warpN + nt * 8 + rB) * KS_B + c * 128 + kk + kB) * 2;
                ldsm_x2(bh[nt][0], bh[nt][1], uBhi + off);
                ldsm_x2(bl[nt][0], bl[nt][1], uBlo + off);
            }
#pragma unroll
            for (int mt = 0; mt < MT; mt++)
#pragma unroll
                for (int nt = 0; nt < NT; nt++) {
                    mma_bf16(acc[mt][nt], ah[mt], bh[nt]);
                    mma_bf16(acc[mt][nt], ah[mt], bl[nt]);
                    mma_bf16(acc[mt][nt], al[mt], bh[nt]);
                }
        }
    }

    // ---- epilogue ----
    int qr = lane >> 2;          // row within m16 (0..7)
    int qc = (lane & 3) * 2;     // col pair within n8
#pragma unroll
    for (int mt = 0; mt < MT; mt++) {
#pragma unroll
        for (int nt = 0; nt < NT; nt++) {
            int n = warpN + nt * 8 + qc;
            float bn0 = sbias[n], bn1 = sbias[n + 1];
#pragma unroll
            for (int half = 0; half < 2; half++) {
                int m = m0 + warpM + mt * 16 + qr + half * 8;
                if (m >= N_NODES) continue;
                float v0 = acc[mt][nt][half * 2 + 0] + bn0;
                float v1 = acc[mt][nt][half * 2 + 1] + bn1;
                if (RELU) { v0 = fmaxf(v0, 0.0f); v1 = fmaxf(v1, 0.0f); }
                if (NOUT == 128) {
                    *(float2*)&out[(long)m * ostride + n] = make_float2(v0, v1);
                    if (SPLIT) {
                        __nv_bfloat16 h0 = __float2bfloat16(v0);
                        __nv_bfloat16 h1 = __float2bfloat16(v1);
                        __nv_bfloat16 l0 = __float2bfloat16(v0 - __bfloat162float(h0));
                        __nv_bfloat16 l1 = __float2bfloat16(v1 - __bfloat162float(h1));
                        *(__nv_bfloat162*)&o_hi[(long)m * 128 + n] = __nv_bfloat162(h0, h1);
                        *(__nv_bfloat162*)&o_lo[(long)m * 128 + n] = __nv_bfloat162(l0, l1);
                    }
                } else {
                    if (n < N_CLS) out[(long)m * ostride + n] = v0;
                    if (n + 1 < N_CLS) out[(long)m * ostride + n + 1] = v1;
                }
            }
        }
    }
}

// ---------------- launch ----------------
extern "C" void kernel_launch(void* const* d_in, const int* in_sizes, int n_in,
                              void* d_out, int out_size) {
    const float* features = (const float*)d_in[0];
    const int*   src      = (const int*)d_in[1];
    const int*   dst      = (const int*)d_in[2];
    const float* Ws0 = (const float*)d_in[3];
    const float* Wn0 = (const float*)d_in[4];
    const float* b0  = (const float*)d_in[5];
    const float* Ws1 = (const float*)d_in[6];
    const float* Wn1 = (const float*)d_in[7];
    const float* b1  = (const float*)d_in[8];
    const float* Ws2 = (const float*)d_in[9];
    const float* Wn2 = (const float*)d_in[10];
    const float* b2  = (const float*)d_in[11];
    float* out = (float*)d_out;

    void* p;
    cudaGetSymbolAddress(&p, g_h1);    float* h1 = (float*)p;
    cudaGetSymbolAddress(&p, g_h2);    float* h2 = (float*)p;
    cudaGetSymbolAddress(&p, g_f_hi);  __nv_bfloat16* f_hi = (__nv_bfloat16*)p;
    cudaGetSymbolAddress(&p, g_f_lo);  __nv_bfloat16* f_lo = (__nv_bfloat16*)p;
    cudaGetSymbolAddress(&p, g_h1_hi); __nv_bfloat16* h1_hi = (__nv_bfloat16*)p;
    cudaGetSymbolAddress(&p, g_h1_lo); __nv_bfloat16* h1_lo = (__nv_bfloat16*)p;
    cudaGetSymbolAddress(&p, g_h2_hi); __nv_bfloat16* h2_hi = (__nv_bfloat16*)p;
    cudaGetSymbolAddress(&p, g_h2_lo); __nv_bfloat16* h2_lo = (__nv_bfloat16*)p;
    cudaGetSymbolAddress(&p, g_B0hi);  __nv_bfloat16* B0h = (__nv_bfloat16*)p;
    cudaGetSymbolAddress(&p, g_B0lo);  __nv_bfloat16* B0l = (__nv_bfloat16*)p;
    cudaGetSymbolAddress(&p, g_B1hi);  __nv_bfloat16* B1h = (__nv_bfloat16*)p;
    cudaGetSymbolAddress(&p, g_B1lo);  __nv_bfloat16* B1l = (__nv_bfloat16*)p;
    cudaGetSymbolAddress(&p, g_B2hi);  __nv_bfloat16* B2h = (__nv_bfloat16*)p;
    cudaGetSymbolAddress(&p, g_B2lo);  __nv_bfloat16* B2l = (__nv_bfloat16*)p;

    // smem: B(hi+lo) NOUT*264 + A(hi+lo) 128*136 + bias
    const int SMEM128 = (2 * 128 * 264 + 2 * 128 * 136) * 2 + 512;  // 205,312
    const int SMEM48  = (2 * 48 * 264 + 2 * 128 * 136) * 2 + 512;   // 120,704
    cudaFuncSetAttribute(gemm_mma<128, true, true>,
                         cudaFuncAttributeMaxDynamicSharedMemorySize, SMEM128);
    cudaFuncSetAttribute(gemm_mma<48, false, false>,
                         cudaFuncAttributeMaxDynamicSharedMemorySize, SMEM48);

    // CSR build
    zero_deg_kernel<<<(N_NODES + 255) / 256, 256>>>();
    count_deg_kernel<<<(N_EDGES + 255) / 256, 256>>>(dst);
    scan_kernel<<<1, 1024>>>();
    fill_csr_kernel<<<(N_EDGES + 255) / 256, 256>>>(src, dst);

    // Weight prep (transpose + concat + hi/lo split)
    prep_B_kernel<<<(128 * 256 + 255) / 256, 256>>>(Ws0, Wn0, 128, 128, B0h, B0l);
    prep_B_kernel<<<(128 * 256 + 255) / 256, 256>>>(Ws1, Wn1, 128, 128, B1h, B1l);
    prep_B_kernel<<<(48 * 256 + 255) / 256, 256>>>(Ws2, Wn2, 47, 48, B2h, B2l);

    // Feature split
    split_kernel<<<(N_NODES * D + 255) / 256, 256>>>(features, f_hi, f_lo, N_NODES * D);

    const int AGG_BLOCKS = (N_NODES * 32 + 255) / 256;
    const int GEMM_BLOCKS = (N_NODES + 127) / 128;  // 391

    // Layer 0
    agg_kernel<<<AGG_BLOCKS, 256>>>(features);
    gemm_mma<128, true, true><<<GEMM_BLOCKS, 256, SMEM128>>>(
        f_hi, f_lo, B0h, B0l, b0, 128, h1, 128, h1_hi, h1_lo);

    // Layer 1
    agg_kernel<<<AGG_BLOCKS, 256>>>(h1);
    gemm_mma<128, true, true><<<GEMM_BLOCKS, 256, SMEM128>>>(
        h1_hi, h1_lo, B1h, B1l, b1, 128, h2, 128, h2_hi, h2_lo);

    // Layer 2 (47 classes, no relu, no split outputs)
    agg_kernel<<<AGG_BLOCKS, 256>>>(h2);
    gemm_mma<48, false, false><<<GEMM_BLOCKS, 256, SMEM48>>>(
        h2_hi, h2_lo, B2h, B2l, b2, 47, out, 47, nullptr, nullptr);
}

// round 4
// speedup vs baseline: 1.3649x; 1.1154x over previous
#include <cuda_runtime.h>
#include <cuda_bf16.h>
#include <cstdint>

#define N_NODES 50000
#define N_EDGES 800000
#define D 128
#define N_CLS 47

// ---------------- scratch (no allocations allowed) ----------------
__device__ int   g_deg[N_NODES];
__device__ int   g_row_ptr[N_NODES + 1];
__device__ int   g_cursor[N_NODES];
__device__ int   g_csr_src[N_EDGES];
__device__ float g_inv_deg[N_NODES];

__device__ __nv_bfloat16 g_f_hi[N_NODES * D];
__device__ __nv_bfloat16 g_f_lo[N_NODES * D];
__device__ __nv_bfloat16 g_h1_hi[N_NODES * D];
__device__ __nv_bfloat16 g_h1_lo[N_NODES * D];
__device__ __nv_bfloat16 g_h2_hi[N_NODES * D];
__device__ __nv_bfloat16 g_h2_lo[N_NODES * D];
__device__ __nv_bfloat16 g_agg_hi[N_NODES * D];
__device__ __nv_bfloat16 g_agg_lo[N_NODES * D];

// Weights pre-transposed + K-concatenated: B[n][k], k in [0,256)
__device__ __nv_bfloat16 g_B0hi[128 * 256];
__device__ __nv_bfloat16 g_B0lo[128 * 256];
__device__ __nv_bfloat16 g_B1hi[128 * 256];
__device__ __nv_bfloat16 g_B1lo[128 * 256];
__device__ __nv_bfloat16 g_B2hi[48 * 256];
__device__ __nv_bfloat16 g_B2lo[48 * 256];

// ---------------- PTX helpers (baseline PTX only) ----------------
__device__ __forceinline__ uint32_t s2u(const void* p) {
    uint32_t a;
    asm("{ .reg .u64 t; cvta.to.shared.u64 t, %1; cvt.u32.u64 %0, t; }" : "=r"(a) : "l"(p));
    return a;
}

__device__ __forceinline__ void ldsm_x4(uint32_t& r0, uint32_t& r1, uint32_t& r2, uint32_t& r3,
                                        uint32_t addr) {
    asm volatile("ldmatrix.sync.aligned.m8n8.x4.shared.b16 {%0,%1,%2,%3}, [%4];"
                 : "=r"(r0), "=r"(r1), "=r"(r2), "=r"(r3) : "r"(addr));
}

__device__ __forceinline__ void ldsm_x2(uint32_t& r0, uint32_t& r1, uint32_t addr) {
    asm volatile("ldmatrix.sync.aligned.m8n8.x2.shared.b16 {%0,%1}, [%2];"
                 : "=r"(r0), "=r"(r1) : "r"(addr));
}

__device__ __forceinline__ void mma_bf16(float* c, const uint32_t* a, const uint32_t* b) {
    asm volatile(
        "mma.sync.aligned.m16n8k16.row.col.f32.bf16.bf16.f32 "
        "{%0,%1,%2,%3}, {%4,%5,%6,%7}, {%8,%9}, {%0,%1,%2,%3};"
        : "+f"(c[0]), "+f"(c[1]), "+f"(c[2]), "+f"(c[3])
        : "r"(a[0]), "r"(a[1]), "r"(a[2]), "r"(a[3]), "r"(b[0]), "r"(b[1]));
}

// ---------------- CSR build ----------------
__global__ void count_deg_kernel(const int* __restrict__ dst) {
    int e = blockIdx.x * blockDim.x + threadIdx.x;
    if (e < N_EDGES) atomicAdd(&g_deg[dst[e]], 1);
}

__global__ void scan_kernel() {
    __shared__ int ssum[1024];
    int tid = threadIdx.x;
    const int CH = (N_NODES + 1023) / 1024;
    int start = tid * CH;
    int end = start + CH;
    if (end > N_NODES) end = N_NODES;
    int s = 0;
    for (int i = start; i < end; i++) s += g_deg[i];
    ssum[tid] = s;
    __syncthreads();
    for (int off = 1; off < 1024; off <<= 1) {
        int v = (tid >= off) ? ssum[tid - off] : 0;
        __syncthreads();
        ssum[tid] += v;
        __syncthreads();
    }
    int run = ssum[tid] - s;
    for (int i = start; i < end; i++) {
        g_row_ptr[i] = run;
        g_cursor[i] = run;
        int d = g_deg[i];
        g_inv_deg[i] = 1.0f / (float)(d > 1 ? d : 1);
        run += d;
    }
    if (tid == 1023) g_row_ptr[N_NODES] = N_EDGES;
}

__global__ void fill_csr_kernel(const int* __restrict__ src, const int* __restrict__ dst) {
    int e = blockIdx.x * blockDim.x + threadIdx.x;
    if (e < N_EDGES) {
        int idx = atomicAdd(&g_cursor[dst[e]], 1);
        g_csr_src[idx] = src[e];
    }
}

// ---------------- weight prep ----------------
__global__ void prep_B_kernel(const float* __restrict__ Ws, const float* __restrict__ Wn,
                              int nreal, int npad,
                              __nv_bfloat16* __restrict__ Bh, __nv_bfloat16* __restrict__ Bl) {
    int i = blockIdx.x * blockDim.x + threadIdx.x;
    if (i >= npad * 256) return;
    int n = i / 256, k = i % 256;
    float w = 0.0f;
    if (n < nreal) w = (k < 128) ? Ws[k * nreal + n] : Wn[(k - 128) * nreal + n];
    __nv_bfloat16 hi = __float2bfloat16(w);
    float rem = w - __bfloat162float(hi);
    Bh[i] = hi;
    Bl[i] = __float2bfloat16(rem);
}

// ---------------- fp32 -> bf16 hi/lo split (features only) ----------------
__global__ void split_kernel(const float* __restrict__ x,
                             __nv_bfloat16* __restrict__ hi, __nv_bfloat16* __restrict__ lo,
                             int n) {
    int i = blockIdx.x * blockDim.x + threadIdx.x;
    if (i >= n) return;
    float v = x[i];
    __nv_bfloat16 h = __float2bfloat16(v);
    hi[i] = h;
    lo[i] = __float2bfloat16(v - __bfloat162float(h));
}

// ---------------- mean aggregation over bf16 hi rows: one warp per node ----------------
// Each lane owns 4 components (8B). fp32 accumulation; hi/lo split output.
__global__ void agg_kernel(const __nv_bfloat16* __restrict__ hsrc) {
    int warp = (blockIdx.x * blockDim.x + threadIdx.x) >> 5;
    int lane = threadIdx.x & 31;
    if (warp >= N_NODES) return;
    int beg = g_row_ptr[warp];
    int end = g_row_ptr[warp + 1];
    float a0 = 0.f, a1 = 0.f, a2 = 0.f, a3 = 0.f;
    int e = beg;
    for (; e + 4 <= end; e += 4) {
        int u0 = __ldg(&g_csr_src[e]);
        int u1 = __ldg(&g_csr_src[e + 1]);
        int u2 = __ldg(&g_csr_src[e + 2]);
        int u3 = __ldg(&g_csr_src[e + 3]);
        uint2 v0 = __ldg((const uint2*)&hsrc[(long)u0 * D + lane * 4]);
        uint2 v1 = __ldg((const uint2*)&hsrc[(long)u1 * D + lane * 4]);
        uint2 v2 = __ldg((const uint2*)&hsrc[(long)u2 * D + lane * 4]);
        uint2 v3 = __ldg((const uint2*)&hsrc[(long)u3 * D + lane * 4]);
#pragma unroll
        for (int j = 0; j < 4; j++) {
            uint2 v = (j == 0) ? v0 : (j == 1) ? v1 : (j == 2) ? v2 : v3;
            float2 p0 = __bfloat1622float2(*(__nv_bfloat162*)&v.x);
            float2 p1 = __bfloat1622float2(*(__nv_bfloat162*)&v.y);
            a0 += p0.x; a1 += p0.y; a2 += p1.x; a3 += p1.y;
        }
    }
    for (; e < end; e++) {
        int u = __ldg(&g_csr_src[e]);
        uint2 v = __ldg((const uint2*)&hsrc[(long)u * D + lane * 4]);
        float2 p0 = __bfloat1622float2(*(__nv_bfloat162*)&v.x);
        float2 p1 = __bfloat1622float2(*(__nv_bfloat162*)&v.y);
        a0 += p0.x; a1 += p0.y; a2 += p1.x; a3 += p1.y;
    }
    float s = g_inv_deg[warp];
    float vals[4] = {a0 * s, a1 * s, a2 * s, a3 * s};
    unsigned short hs[4], ls[4];
#pragma unroll
    for (int j = 0; j < 4; j++) {
        __nv_bfloat16 hv = __float2bfloat16(vals[j]);
        hs[j] = __bfloat16_as_ushort(hv);
        ls[j] = __bfloat16_as_ushort(__float2bfloat16(vals[j] - __bfloat162float(hv)));
    }
    long off = (long)warp * D + lane * 4;
    *(ushort4*)&g_agg_hi[off] = make_ushort4(hs[0], hs[1], hs[2], hs[3]);
    *(ushort4*)&g_agg_lo[off] = make_ushort4(ls[0], ls[1], ls[2], ls[3]);
}

// ---------------- HMMA fused GEMM: D[128,NOUT] = [x|agg](hi+lo) @ B(hi+lo)^T + b ----------------
// Error-split: acc = a_hi*b_hi + a_hi*b_lo + a_lo*b_hi
template <int NOUT, bool RELU, bool SPLIT, bool WF32>
__global__ void __launch_bounds__(256, 1) gemm_mma(
    const __nv_bfloat16* __restrict__ x_hi, const __nv_bfloat16* __restrict__ x_lo,
    const __nv_bfloat16* __restrict__ Bhi_g, const __nv_bfloat16* __restrict__ Blo_g,
    const float* __restrict__ bias, int nbias,
    float* __restrict__ out, int ostride,
    __nv_bfloat16* __restrict__ o_hi, __nv_bfloat16* __restrict__ o_lo) {
    constexpr int KS_B = 264;
    constexpr int KS_A = 136;
    constexpr int MT = (NOUT == 128) ? 2 : 1;
    constexpr int NT = (NOUT == 128) ? 8 : 6;

    extern __shared__ __nv_bfloat16 sm[];
    __nv_bfloat16* sBhi = sm;
    __nv_bfloat16* sBlo = sBhi + NOUT * KS_B;
    __nv_bfloat16* sAhi = sBlo + NOUT * KS_B;
    __nv_bfloat16* sAlo = sAhi + 128 * KS_A;
    float* sbias = (float*)(sAlo + 128 * KS_A);

    int tid = threadIdx.x;
    int wid = tid >> 5;
    int lane = tid & 31;
    int m0 = blockIdx.x * 128;

    int warpM = (NOUT == 128) ? (wid & 3) * 32 : wid * 16;
    int warpN = (NOUT == 128) ? (wid >> 2) * 64 : 0;

    for (int i = tid; i < NOUT * 32; i += 256) {
        int n = i >> 5;
        int k8 = (i & 31) << 3;
        *(uint4*)&sBhi[n * KS_B + k8] = *(const uint4*)&Bhi_g[n * 256 + k8];
        *(uint4*)&sBlo[n * KS_B + k8] = *(const uint4*)&Blo_g[n * 256 + k8];
    }
    if (tid < NOUT) sbias[tid] = (tid < nbias) ? bias[tid] : 0.0f;

    float acc[MT][NT][4];
#pragma unroll
    for (int mt = 0; mt < MT; mt++)
#pragma unroll
        for (int nt = 0; nt < NT; nt++)
#pragma unroll
            for (int j = 0; j < 4; j++) acc[mt][nt][j] = 0.0f;

    uint32_t uAhi = s2u(sAhi), uAlo = s2u(sAlo);
    uint32_t uBhi = s2u(sBhi), uBlo = s2u(sBlo);

    int g = lane >> 3;
    int rA = (g & 1) * 8 + (lane & 7);
    int kA = (g >> 1) * 8;
    int rB = lane & 7;
    int kB = ((lane >> 3) & 1) * 8;

#pragma unroll 1
    for (int c = 0; c < 2; c++) {
        const __nv_bfloat16* shi = (c == 0) ? x_hi : g_agg_hi;
        const __nv_bfloat16* slo = (c == 0) ? x_lo : g_agg_lo;
        __syncthreads();
        for (int i = tid; i < 128 * 16; i += 256) {
            int r = i >> 4;
            int k8 = (i & 15) << 3;
            int m = m0 + r;
            uint4 vh = make_uint4(0, 0, 0, 0), vl = make_uint4(0, 0, 0, 0);
            if (m < N_NODES) {
                vh = *(const uint4*)&shi[(long)m * 128 + k8];
                vl = *(const uint4*)&slo[(long)m * 128 + k8];
            }
            *(uint4*)&sAhi[r * KS_A + k8] = vh;
            *(uint4*)&sAlo[r * KS_A + k8] = vl;
        }
        __syncthreads();

#pragma unroll
        for (int kk = 0; kk < 128; kk += 16) {
            uint32_t ah[MT][4], al[MT][4];
#pragma unroll
            for (int mt = 0; mt < MT; mt++) {
                uint32_t off = (uint32_t)((warpM + mt * 16 + rA) * KS_A + kk + kA) * 2;
                ldsm_x4(ah[mt][0], ah[mt][1], ah[mt][2], ah[mt][3], uAhi + off);
                ldsm_x4(al[mt][0], al[mt][1], al[mt][2], al[mt][3], uAlo + off);
            }
            uint32_t bh[NT][2], bl[NT][2];
#pragma unroll
            for (int nt = 0; nt < NT; nt++) {
                uint32_t off = (uint32_t)((warpN + nt * 8 + rB) * KS_B + c * 128 + kk + kB) * 2;
                ldsm_x2(bh[nt][0], bh[nt][1], uBhi + off);
                ldsm_x2(bl[nt][0], bl[nt][1], uBlo + off);
            }
#pragma unroll
            for (int mt = 0; mt < MT; mt++)
#pragma unroll
                for (int nt = 0; nt < NT; nt++) {
                    mma_bf16(acc[mt][nt], ah[mt], bh[nt]);
                    mma_bf16(acc[mt][nt], ah[mt], bl[nt]);
                    mma_bf16(acc[mt][nt], al[mt], bh[nt]);
                }
        }
    }

    // ---- epilogue ----
    int qr = lane >> 2;
    int qc = (lane & 3) * 2;
#pragma unroll
    for (int mt = 0; mt < MT; mt++) {
#pragma unroll
        for (int nt = 0; nt < NT; nt++) {
            int n = warpN + nt * 8 + qc;
            float bn0 = sbias[n], bn1 = sbias[n + 1];
#pragma unroll
            for (int half = 0; half < 2; half++) {
                int m = m0 + warpM + mt * 16 + qr + half * 8;
                if (m >= N_NODES) continue;
                float v0 = acc[mt][nt][half * 2 + 0] + bn0;
                float v1 = acc[mt][nt][half * 2 + 1] + bn1;
                if (RELU) { v0 = fmaxf(v0, 0.0f); v1 = fmaxf(v1, 0.0f); }
                if (NOUT == 128) {
                    if (WF32) *(float2*)&out[(long)m * ostride + n] = make_float2(v0, v1);
                    if (SPLIT) {
                        __nv_bfloat16 h0 = __float2bfloat16(v0);
                        __nv_bfloat16 h1 = __float2bfloat16(v1);
                        __nv_bfloat16 l0 = __float2bfloat16(v0 - __bfloat162float(h0));
                        __nv_bfloat16 l1 = __float2bfloat16(v1 - __bfloat162float(h1));
                        *(__nv_bfloat162*)&o_hi[(long)m * 128 + n] = __nv_bfloat162(h0, h1);
                        *(__nv_bfloat162*)&o_lo[(long)m * 128 + n] = __nv_bfloat162(l0, l1);
                    }
                } else {
                    if (n < N_CLS) out[(long)m * ostride + n] = v0;
                    if (n + 1 < N_CLS) out[(long)m * ostride + n + 1] = v1;
                }
            }
        }
    }
}

// ---------------- launch ----------------
extern "C" void kernel_launch(void* const* d_in, const int* in_sizes, int n_in,
                              void* d_out, int out_size) {
    const float* features = (const float*)d_in[0];
    const int*   src      = (const int*)d_in[1];
    const int*   dst      = (const int*)d_in[2];
    const float* Ws0 = (const float*)d_in[3];
    const float* Wn0 = (const float*)d_in[4];
    const float* b0  = (const float*)d_in[5];
    const float* Ws1 = (const float*)d_in[6];
    const float* Wn1 = (const float*)d_in[7];
    const float* b1  = (const float*)d_in[8];
    const float* Ws2 = (const float*)d_in[9];
    const float* Wn2 = (const float*)d_in[10];
    const float* b2  = (const float*)d_in[11];
    float* out = (float*)d_out;

    void* p;
    cudaGetSymbolAddress(&p, g_f_hi);  __nv_bfloat16* f_hi = (__nv_bfloat16*)p;
    cudaGetSymbolAddress(&p, g_f_lo);  __nv_bfloat16* f_lo = (__nv_bfloat16*)p;
    cudaGetSymbolAddress(&p, g_h1_hi); __nv_bfloat16* h1_hi = (__nv_bfloat16*)p;
    cudaGetSymbolAddress(&p, g_h1_lo); __nv_bfloat16* h1_lo = (__nv_bfloat16*)p;
    cudaGetSymbolAddress(&p, g_h2_hi); __nv_bfloat16* h2_hi = (__nv_bfloat16*)p;
    cudaGetSymbolAddress(&p, g_h2_lo); __nv_bfloat16* h2_lo = (__nv_bfloat16*)p;
    cudaGetSymbolAddress(&p, g_B0hi);  __nv_bfloat16* B0h = (__nv_bfloat16*)p;
    cudaGetSymbolAddress(&p, g_B0lo);  __nv_bfloat16* B0l = (__nv_bfloat16*)p;
    cudaGetSymbolAddress(&p, g_B1hi);  __nv_bfloat16* B1h = (__nv_bfloat16*)p;
    cudaGetSymbolAddress(&p, g_B1lo);  __nv_bfloat16* B1l = (__nv_bfloat16*)p;
    cudaGetSymbolAddress(&p, g_B2hi);  __nv_bfloat16* B2h = (__nv_bfloat16*)p;
    cudaGetSymbolAddress(&p, g_B2lo);  __nv_bfloat16* B2l = (__nv_bfloat16*)p;
    void* degp; cudaGetSymbolAddress(&degp, g_deg);

    const int SMEM128 = (2 * 128 * 264 + 2 * 128 * 136) * 2 + 512;  // 205,312
    const int SMEM48  = (2 * 48 * 264 + 2 * 128 * 136) * 2 + 512;   // 120,704
    cudaFuncSetAttribute(gemm_mma<128, true, true, false>,
                         cudaFuncAttributeMaxDynamicSharedMemorySize, SMEM128);
    cudaFuncSetAttribute(gemm_mma<48, false, false, true>,
                         cudaFuncAttributeMaxDynamicSharedMemorySize, SMEM48);

    // CSR build
    cudaMemsetAsync(degp, 0, N_NODES * sizeof(int));
    count_deg_kernel<<<(N_EDGES + 255) / 256, 256>>>(dst);
    scan_kernel<<<1, 1024>>>();
    fill_csr_kernel<<<(N_EDGES + 255) / 256, 256>>>(src, dst);

    // Weight prep + feature split
    prep_B_kernel<<<(128 * 256 + 255) / 256, 256>>>(Ws0, Wn0, 128, 128, B0h, B0l);
    prep_B_kernel<<<(128 * 256 + 255) / 256, 256>>>(Ws1, Wn1, 128, 128, B1h, B1l);
    prep_B_kernel<<<(48 * 256 + 255) / 256, 256>>>(Ws2, Wn2, 47, 48, B2h, B2l);
    split_kernel<<<(N_NODES * D + 255) / 256, 256>>>(features, f_hi, f_lo, N_NODES * D);

    const int AGG_BLOCKS = (N_NODES * 32 + 255) / 256;
    const int GEMM_BLOCKS = (N_NODES + 127) / 128;  // 391

    // Layer 0
    agg_kernel<<<AGG_BLOCKS, 256>>>(f_hi);
    gemm_mma<128, true, true, false><<<GEMM_BLOCKS, 256, SMEM128>>>(
        f_hi, f_lo, B0h, B0l, b0, 128, nullptr, 128, h1_hi, h1_lo);

    // Layer 1
    agg_kernel<<<AGG_BLOCKS, 256>>>(h1_hi);
    gemm_mma<128, true, true, false><<<GEMM_BLOCKS, 256, SMEM128>>>(
        h1_hi, h1_lo, B1h, B1l, b1, 128, nullptr, 128, h2_hi, h2_lo);

    // Layer 2 (47 classes, no relu)
    agg_kernel<<<AGG_BLOCKS, 256>>>(h2_hi);
    gemm_mma<48, false, false, true><<<GEMM_BLOCKS, 256, SMEM48>>>(
        h2_hi, h2_lo, B2h, B2l, b2, 47, out, 47, nullptr, nullptr);
}

// round 5
// speedup vs baseline: 1.3941x; 1.0214x over previous
#include <cuda_runtime.h>
#include <cuda_fp16.h>
#include <cstdint>

#define N_NODES 50000
#define N_EDGES 800000
#define D 128
#define N_CLS 47

// ---------------- scratch (no allocations allowed) ----------------
__device__ int   g_deg[N_NODES];
__device__ int   g_row_ptr[N_NODES + 1];
__device__ int   g_cursor[N_NODES];
__device__ int   g_csr_src[N_EDGES];
__device__ float g_inv_deg[N_NODES];

__device__ __half g_f_hi[N_NODES * D];
__device__ __half g_f_lo[N_NODES * D];
__device__ __half g_h1_hi[N_NODES * D];
__device__ __half g_h1_lo[N_NODES * D];
__device__ __half g_h2_hi[N_NODES * D];
__device__ __half g_h2_lo[N_NODES * D];
__device__ __half g_agg_hi[N_NODES * D];
__device__ __half g_agg_lo[N_NODES * D];

// Weights pre-transposed + K-concatenated: B[n][k], k in [0,256)
__device__ __half g_B0hi[128 * 256];
__device__ __half g_B0lo[128 * 256];
__device__ __half g_B1hi[128 * 256];
__device__ __half g_B1lo[128 * 256];
__device__ __half g_B2hi[48 * 256];
__device__ __half g_B2lo[48 * 256];

// ---------------- PTX helpers (baseline PTX only) ----------------
__device__ __forceinline__ uint32_t s2u(const void* p) {
    uint32_t a;
    asm("{ .reg .u64 t; cvta.to.shared.u64 t, %1; cvt.u32.u64 %0, t; }" : "=r"(a) : "l"(p));
    return a;
}

__device__ __forceinline__ void ldsm_x4(uint32_t& r0, uint32_t& r1, uint32_t& r2, uint32_t& r3,
                                        uint32_t addr) {
    asm volatile("ldmatrix.sync.aligned.m8n8.x4.shared.b16 {%0,%1,%2,%3}, [%4];"
                 : "=r"(r0), "=r"(r1), "=r"(r2), "=r"(r3) : "r"(addr));
}

__device__ __forceinline__ void ldsm_x2(uint32_t& r0, uint32_t& r1, uint32_t addr) {
    asm volatile("ldmatrix.sync.aligned.m8n8.x2.shared.b16 {%0,%1}, [%2];"
                 : "=r"(r0), "=r"(r1) : "r"(addr));
}

__device__ __forceinline__ void mma_f16(float* c, const uint32_t* a, const uint32_t* b) {
    asm volatile(
        "mma.sync.aligned.m16n8k16.row.col.f32.f16.f16.f32 "
        "{%0,%1,%2,%3}, {%4,%5,%6,%7}, {%8,%9}, {%0,%1,%2,%3};"
        : "+f"(c[0]), "+f"(c[1]), "+f"(c[2]), "+f"(c[3])
        : "r"(a[0]), "r"(a[1]), "r"(a[2]), "r"(a[3]), "r"(b[0]), "r"(b[1]));
}

__device__ __forceinline__ void split2(float v, unsigned short& h, unsigned short& l) {
    __half hv = __float2half_rn(v);
    h = __half_as_ushort(hv);
    l = __half_as_ushort(__float2half_rn(v - __half2float(hv)));
}

// ---------------- CSR build ----------------
__global__ void count_deg_kernel(const int* __restrict__ dst) {
    int e = blockIdx.x * blockDim.x + threadIdx.x;
    if (e < N_EDGES) atomicAdd(&g_deg[dst[e]], 1);
}

__global__ void scan_kernel() {
    __shared__ int ssum[1024];
    int tid = threadIdx.x;
    const int CH = (N_NODES + 1023) / 1024;
    int start = tid * CH;
    int end = start + CH;
    if (end > N_NODES) end = N_NODES;
    int s = 0;
    for (int i = start; i < end; i++) s += g_deg[i];
    ssum[tid] = s;
    __syncthreads();
    for (int off = 1; off < 1024; off <<= 1) {
        int v = (tid >= off) ? ssum[tid - off] : 0;
        __syncthreads();
        ssum[tid] += v;
        __syncthreads();
    }
    int run = ssum[tid] - s;
    for (int i = start; i < end; i++) {
        g_row_ptr[i] = run;
        g_cursor[i] = run;
        int d = g_deg[i];
        g_inv_deg[i] = 1.0f / (float)(d > 1 ? d : 1);
        run += d;
    }
    if (tid == 1023) g_row_ptr[N_NODES] = N_EDGES;
}

__global__ void fill_csr_kernel(const int* __restrict__ src, const int* __restrict__ dst) {
    int e = blockIdx.x * blockDim.x + threadIdx.x;
    if (e < N_EDGES) {
        int idx = atomicAdd(&g_cursor[dst[e]], 1);
        g_csr_src[idx] = src[e];
    }
}

// ---------------- fused weight prep for all 3 layers ----------------
__global__ void prep_all_kernel(const float* __restrict__ Ws0, const float* __restrict__ Wn0,
                                const float* __restrict__ Ws1, const float* __restrict__ Wn1,
                                const float* __restrict__ Ws2, const float* __restrict__ Wn2) {
    int layer = blockIdx.y;
    int i = blockIdx.x * blockDim.x + threadIdx.x;
    const float* Ws;
    const float* Wn;
    __half* Bh;
    __half* Bl;
    int nreal, npad;
    if (layer == 0) { Ws = Ws0; Wn = Wn0; Bh = g_B0hi; Bl = g_B0lo; nreal = 128; npad = 128; }
    else if (layer == 1) { Ws = Ws1; Wn = Wn1; Bh = g_B1hi; Bl = g_B1lo; nreal = 128; npad = 128; }
    else { Ws = Ws2; Wn = Wn2; Bh = g_B2hi; Bl = g_B2lo; nreal = 47; npad = 48; }
    if (i >= npad * 256) return;
    int n = i / 256, k = i % 256;
    float w = 0.0f;
    if (n < nreal) w = (k < 128) ? Ws[k * nreal + n] : Wn[(k - 128) * nreal + n];
    unsigned short h, l;
    split2(w, h, l);
    Bh[i] = __ushort_as_half(h);
    Bl[i] = __ushort_as_half(l);
}

// ---------------- fp32 -> fp16 hi/lo split (features) ----------------
__global__ void split_kernel(const float* __restrict__ x,
                             __half* __restrict__ hi, __half* __restrict__ lo, int n) {
    int i = blockIdx.x * blockDim.x + threadIdx.x;
    if (i >= n) return;
    unsigned short h, l;
    split2(x[i], h, l);
    hi[i] = __ushort_as_half(h);
    lo[i] = __ushort_as_half(l);
}

// ---------------- mean aggregation over fp16 hi rows: one warp per node ----------------
__global__ void agg_kernel(const __half* __restrict__ hsrc) {
    int warp = (blockIdx.x * blockDim.x + threadIdx.x) >> 5;
    int lane = threadIdx.x & 31;
    if (warp >= N_NODES) return;
    int beg = g_row_ptr[warp];
    int end = g_row_ptr[warp + 1];
    float a0 = 0.f, a1 = 0.f, a2 = 0.f, a3 = 0.f;
    int e = beg;
    for (; e + 4 <= end; e += 4) {
        int u0 = __ldg(&g_csr_src[e]);
        int u1 = __ldg(&g_csr_src[e + 1]);
        int u2 = __ldg(&g_csr_src[e + 2]);
        int u3 = __ldg(&g_csr_src[e + 3]);
        uint2 v0 = __ldg((const uint2*)&hsrc[(long)u0 * D + lane * 4]);
        uint2 v1 = __ldg((const uint2*)&hsrc[(long)u1 * D + lane * 4]);
        uint2 v2 = __ldg((const uint2*)&hsrc[(long)u2 * D + lane * 4]);
        uint2 v3 = __ldg((const uint2*)&hsrc[(long)u3 * D + lane * 4]);
#pragma unroll
        for (int j = 0; j < 4; j++) {
            uint2 v = (j == 0) ? v0 : (j == 1) ? v1 : (j == 2) ? v2 : v3;
            float2 p0 = __half22float2(*(__half2*)&v.x);
            float2 p1 = __half22float2(*(__half2*)&v.y);
            a0 += p0.x; a1 += p0.y; a2 += p1.x; a3 += p1.y;
        }
    }
    for (; e < end; e++) {
        int u = __ldg(&g_csr_src[e]);
        uint2 v = __ldg((const uint2*)&hsrc[(long)u * D + lane * 4]);
        float2 p0 = __half22float2(*(__half2*)&v.x);
        float2 p1 = __half22float2(*(__half2*)&v.y);
        a0 += p0.x; a1 += p0.y; a2 += p1.x; a3 += p1.y;
    }
    float s = g_inv_deg[warp];
    float vals[4] = {a0 * s, a1 * s, a2 * s, a3 * s};
    unsigned short hs[4], ls[4];
#pragma unroll
    for (int j = 0; j < 4; j++) split2(vals[j], hs[j], ls[j]);
    long off = (long)warp * D + lane * 4;
    *(ushort4*)&g_agg_hi[off] = make_ushort4(hs[0], hs[1], hs[2], hs[3]);
    *(ushort4*)&g_agg_lo[off] = make_ushort4(ls[0], ls[1], ls[2], ls[3]);
}

// ---------------- HMMA fused GEMM: D[128,NOUT] = [x|agg](hi+lo) @ B(hi+lo)^T + b ----------------
// Error-split: acc = a_hi*b_hi + a_hi*b_lo + a_lo*b_hi
template <int NOUT, bool RELU, bool SPLIT, bool WF32>
__global__ void __launch_bounds__(256, 1) gemm_mma(
    const __half* __restrict__ x_hi, const __half* __restrict__ x_lo,
    const __half* __restrict__ Bhi_g, const __half* __restrict__ Blo_g,
    const float* __restrict__ bias, int nbias,
    float* __restrict__ out, int ostride,
    __half* __restrict__ o_hi, __half* __restrict__ o_lo) {
    constexpr int KS_B = 264;
    constexpr int KS_A = 136;
    constexpr int MT = (NOUT == 128) ? 2 : 1;
    constexpr int NT = (NOUT == 128) ? 8 : 6;

    extern __shared__ __half sm[];
    __half* sBhi = sm;
    __half* sBlo = sBhi + NOUT * KS_B;
    __half* sAhi = sBlo + NOUT * KS_B;
    __half* sAlo = sAhi + 128 * KS_A;
    float* sbias = (float*)(sAlo + 128 * KS_A);

    int tid = threadIdx.x;
    int wid = tid >> 5;
    int lane = tid & 31;
    int m0 = blockIdx.x * 128;

    int warpM = (NOUT == 128) ? (wid & 3) * 32 : wid * 16;
    int warpN = (NOUT == 128) ? (wid >> 2) * 64 : 0;

    for (int i = tid; i < NOUT * 32; i += 256) {
        int n = i >> 5;
        int k8 = (i & 31) << 3;
        *(uint4*)&sBhi[n * KS_B + k8] = *(const uint4*)&Bhi_g[n * 256 + k8];
        *(uint4*)&sBlo[n * KS_B + k8] = *(const uint4*)&Blo_g[n * 256 + k8];
    }
    if (tid < NOUT) sbias[tid] = (tid < nbias) ? bias[tid] : 0.0f;

    float acc[MT][NT][4];
#pragma unroll
    for (int mt = 0; mt < MT; mt++)
#pragma unroll
        for (int nt = 0; nt < NT; nt++)
#pragma unroll
            for (int j = 0; j < 4; j++) acc[mt][nt][j] = 0.0f;

    uint32_t uAhi = s2u(sAhi), uAlo = s2u(sAlo);
    uint32_t uBhi = s2u(sBhi), uBlo = s2u(sBlo);

    int g = lane >> 3;
    int rA = (g & 1) * 8 + (lane & 7);
    int kA = (g >> 1) * 8;
    int rB = lane & 7;
    int kB = ((lane >> 3) & 1) * 8;

#pragma unroll 1
    for (int c = 0; c < 2; c++) {
        const __half* shi = (c == 0) ? x_hi : g_agg_hi;
        const __half* slo = (c == 0) ? x_lo : g_agg_lo;
        __syncthreads();
        for (int i = tid; i < 128 * 16; i += 256) {
            int r = i >> 4;
            int k8 = (i & 15) << 3;
            int m = m0 + r;
            uint4 vh = make_uint4(0, 0, 0, 0), vl = make_uint4(0, 0, 0, 0);
            if (m < N_NODES) {
                vh = *(const uint4*)&shi[(long)m * 128 + k8];
                vl = *(const uint4*)&slo[(long)m * 128 + k8];
            }
            *(uint4*)&sAhi[r * KS_A + k8] = vh;
            *(uint4*)&sAlo[r * KS_A + k8] = vl;
        }
        __syncthreads();

#pragma unroll
        for (int kk = 0; kk < 128; kk += 16) {
            uint32_t ah[MT][4], al[MT][4];
#pragma unroll
            for (int mt = 0; mt < MT; mt++) {
                uint32_t off = (uint32_t)((warpM + mt * 16 + rA) * KS_A + kk + kA) * 2;
                ldsm_x4(ah[mt][0], ah[mt][1], ah[mt][2], ah[mt][3], uAhi + off);
                ldsm_x4(al[mt][0], al[mt][1], al[mt][2], al[mt][3], uAlo + off);
            }
            uint32_t bh[NT][2], bl[NT][2];
#pragma unroll
            for (int nt = 0; nt < NT; nt++) {
                uint32_t off = (uint32_t)((warpN + nt * 8 + rB) * KS_B + c * 128 + kk + kB) * 2;
                ldsm_x2(bh[nt][0], bh[nt][1], uBhi + off);
                ldsm_x2(bl[nt][0], bl[nt][1], uBlo + off);
            }
#pragma unroll
            for (int mt = 0; mt < MT; mt++)
#pragma unroll
                for (int nt = 0; nt < NT; nt++) {
                    mma_f16(acc[mt][nt], ah[mt], bh[nt]);
                    mma_f16(acc[mt][nt], ah[mt], bl[nt]);
                    mma_f16(acc[mt][nt], al[mt], bh[nt]);
                }
        }
    }

    // ---- epilogue ----
    int qr = lane >> 2;
    int qc = (lane & 3) * 2;
#pragma unroll
    for (int mt = 0; mt < MT; mt++) {
#pragma unroll
        for (int nt = 0; nt < NT; nt++) {
            int n = warpN + nt * 8 + qc;
            float bn0 = sbias[n], bn1 = sbias[n + 1];
#pragma unroll
            for (int half = 0; half < 2; half++) {
                int m = m0 + warpM + mt * 16 + qr + half * 8;
                if (m >= N_NODES) continue;
                float v0 = acc[mt][nt][half * 2 + 0] + bn0;
                float v1 = acc[mt][nt][half * 2 + 1] + bn1;
                if (RELU) { v0 = fmaxf(v0, 0.0f); v1 = fmaxf(v1, 0.0f); }
                if (NOUT == 128) {
                    if (WF32) *(float2*)&out[(long)m * ostride + n] = make_float2(v0, v1);
                    if (SPLIT) {
                        unsigned short h0, h1, l0, l1;
                        split2(v0, h0, l0);
                        split2(v1, h1, l1);
                        *(uint32_t*)&o_hi[(long)m * 128 + n] = (uint32_t)h0 | ((uint32_t)h1 << 16);
                        *(uint32_t*)&o_lo[(long)m * 128 + n] = (uint32_t)l0 | ((uint32_t)l1 << 16);
                    }
                } else {
                    if (n < N_CLS) out[(long)m * ostride + n] = v0;
                    if (n + 1 < N_CLS) out[(long)m * ostride + n + 1] = v1;
                }
            }
        }
    }
}

// ---------------- launch ----------------
extern "C" void kernel_launch(void* const* d_in, const int* in_sizes, int n_in,
                              void* d_out, int out_size) {
    const float* features = (const float*)d_in[0];
    const int*   src      = (const int*)d_in[1];
    const int*   dst      = (const int*)d_in[2];
    const float* Ws0 = (const float*)d_in[3];
    const float* Wn0 = (const float*)d_in[4];
    const float* b0  = (const float*)d_in[5];
    const float* Ws1 = (const float*)d_in[6];
    const float* Wn1 = (const float*)d_in[7];
    const float* b1  = (const float*)d_in[8];
    const float* Ws2 = (const float*)d_in[9];
    const float* Wn2 = (const float*)d_in[10];
    const float* b2  = (const float*)d_in[11];
    float* out = (float*)d_out;

    void* p;
    cudaGetSymbolAddress(&p, g_f_hi);  __half* f_hi = (__half*)p;
    cudaGetSymbolAddress(&p, g_f_lo);  __half* f_lo = (__half*)p;
    cudaGetSymbolAddress(&p, g_h1_hi); __half* h1_hi = (__half*)p;
    cudaGetSymbolAddress(&p, g_h1_lo); __half* h1_lo = (__half*)p;
    cudaGetSymbolAddress(&p, g_h2_hi); __half* h2_hi = (__half*)p;
    cudaGetSymbolAddress(&p, g_h2_lo); __half* h2_lo = (__half*)p;
    cudaGetSymbolAddress(&p, g_B0hi);  __half* B0h = (__half*)p;
    cudaGetSymbolAddress(&p, g_B0lo);  __half* B0l = (__half*)p;
    cudaGetSymbolAddress(&p, g_B1hi);  __half* B1h = (__half*)p;
    cudaGetSymbolAddress(&p, g_B1lo);  __half* B1l = (__half*)p;
    cudaGetSymbolAddress(&p, g_B2hi);  __half* B2h = (__half*)p;
    cudaGetSymbolAddress(&p, g_B2lo);  __half* B2l = (__half*)p;
    void* degp; cudaGetSymbolAddress(&degp, g_deg);

    const int SMEM128 = (2 * 128 * 264 + 2 * 128 * 136) * 2 + 512;  // 205,312
    const int SMEM48  = (2 * 48 * 264 + 2 * 128 * 136) * 2 + 512;   // 120,704
    cudaFuncSetAttribute(gemm_mma<128, true, true, false>,
                         cudaFuncAttributeMaxDynamicSharedMemorySize, SMEM128);
    cudaFuncSetAttribute(gemm_mma<48, false, false, true>,
                         cudaFuncAttributeMaxDynamicSharedMemorySize, SMEM48);

    // Fork: CSR chain on main stream, weight-prep + feature-split on s2.
    cudaStream_t s2;
    cudaStreamCreateWithFlags(&s2, cudaStreamNonBlocking);
    cudaEvent_t e_fork, e_join;
    cudaEventCreateWithFlags(&e_fork, cudaEventDisableTiming);
    cudaEventCreateWithFlags(&e_join, cudaEventDisableTiming);

    cudaEventRecord(e_fork, 0);
    cudaStreamWaitEvent(s2, e_fork, 0);

    // s2: prep + split
    prep_all_kernel<<<dim3(128, 3), 256, 0, s2>>>(Ws0, Wn0, Ws1, Wn1, Ws2, Wn2);
    split_kernel<<<(N_NODES * D + 255) / 256, 256, 0, s2>>>(features, f_hi, f_lo, N_NODES * D);
    cudaEventRecord(e_join, s2);

    // main: CSR build
    cudaMemsetAsync(degp, 0, N_NODES * sizeof(int));
    count_deg_kernel<<<(N_EDGES + 255) / 256, 256>>>(dst);
    scan_kernel<<<1, 1024>>>();
    fill_csr_kernel<<<(N_EDGES + 255) / 256, 256>>>(src, dst);

    cudaStreamWaitEvent(0, e_join, 0);

    const int AGG_BLOCKS = (N_NODES * 32 + 255) / 256;
    const int GEMM_BLOCKS = (N_NODES + 127) / 128;  // 391

    // Layer 0
    agg_kernel<<<AGG_BLOCKS, 256>>>(f_hi);
    gemm_mma<128, true, true, false><<<GEMM_BLOCKS, 256, SMEM128>>>(
        f_hi, f_lo, B0h, B0l, b0, 128, nullptr, 128, h1_hi, h1_lo);

    // Layer 1
    agg_kernel<<<AGG_BLOCKS, 256>>>(h1_hi);
    gemm_mma<128, true, true, false><<<GEMM_BLOCKS, 256, SMEM128>>>(
        h1_hi, h1_lo, B1h, B1l, b1, 128, nullptr, 128, h2_hi, h2_lo);

    // Layer 2 (47 classes, no relu)
    agg_kernel<<<AGG_BLOCKS, 256>>>(h2_hi);
    gemm_mma<48, false, false, true><<<GEMM_BLOCKS, 256, SMEM48>>>(
        h2_hi, h2_lo, B2h, B2l, b2, 47, out, 47, nullptr, nullptr);
}

// round 6
// speedup vs baseline: 1.9367x; 1.3892x over previous
#include <cuda_runtime.h>
#include <cuda_fp16.h>
#include <cstdint>

#define N_NODES 50000
#define N_EDGES 800000
#define D 128
#define N_CLS 47

#define SCAN_CHUNK 512
#define SCAN_BLOCKS ((N_NODES + SCAN_CHUNK - 1) / SCAN_CHUNK)  // 98

// ---------------- scratch (no allocations allowed) ----------------
__device__ int   g_deg[N_NODES];
__device__ int   g_row_ptr[N_NODES + 1];
__device__ int   g_cursor[N_NODES];
__device__ int   g_csr_src[N_EDGES];
__device__ float g_inv_deg[N_NODES];
__device__ int   g_blk_sum[SCAN_BLOCKS];
__device__ int   g_blk_off[SCAN_BLOCKS];

__device__ __half g_f_hi[N_NODES * D];
__device__ __half g_f_lo[N_NODES * D];
__device__ __half g_h1_hi[N_NODES * D];
__device__ __half g_h1_lo[N_NODES * D];
__device__ __half g_h2_hi[N_NODES * D];
__device__ __half g_h2_lo[N_NODES * D];
__device__ __half g_agg_hi[N_NODES * D];
__device__ __half g_agg_lo[N_NODES * D];

// Weights pre-transposed + K-concatenated: B[n][k], k in [0,256)
__device__ __half g_B0hi[128 * 256];
__device__ __half g_B0lo[128 * 256];
__device__ __half g_B1hi[128 * 256];
__device__ __half g_B1lo[128 * 256];
__device__ __half g_B2hi[48 * 256];
__device__ __half g_B2lo[48 * 256];

// ---------------- PTX helpers (baseline PTX only) ----------------
__device__ __forceinline__ uint32_t s2u(const void* p) {
    uint32_t a;
    asm("{ .reg .u64 t; cvta.to.shared.u64 t, %1; cvt.u32.u64 %0, t; }" : "=r"(a) : "l"(p));
    return a;
}

__device__ __forceinline__ void ldsm_x4(uint32_t& r0, uint32_t& r1, uint32_t& r2, uint32_t& r3,
                                        uint32_t addr) {
    asm volatile("ldmatrix.sync.aligned.m8n8.x4.shared.b16 {%0,%1,%2,%3}, [%4];"
                 : "=r"(r0), "=r"(r1), "=r"(r2), "=r"(r3) : "r"(addr));
}

__device__ __forceinline__ void ldsm_x2(uint32_t& r0, uint32_t& r1, uint32_t addr) {
    asm volatile("ldmatrix.sync.aligned.m8n8.x2.shared.b16 {%0,%1}, [%2];"
                 : "=r"(r0), "=r"(r1) : "r"(addr));
}

__device__ __forceinline__ void mma_f16(float* c, const uint32_t* a, const uint32_t* b) {
    asm volatile(
        "mma.sync.aligned.m16n8k16.row.col.f32.f16.f16.f32 "
        "{%0,%1,%2,%3}, {%4,%5,%6,%7}, {%8,%9}, {%0,%1,%2,%3};"
        : "+f"(c[0]), "+f"(c[1]), "+f"(c[2]), "+f"(c[3])
        : "r"(a[0]), "r"(a[1]), "r"(a[2]), "r"(a[3]), "r"(b[0]), "r"(b[1]));
}

__device__ __forceinline__ void split2(float v, unsigned short& h, unsigned short& l) {
    __half hv = __float2half_rn(v);
    h = __half_as_ushort(hv);
    l = __half_as_ushort(__float2half_rn(v - __half2float(hv)));
}

// ---------------- CSR build ----------------
__global__ void count_deg_kernel(const int* __restrict__ dst) {
    int e = blockIdx.x * blockDim.x + threadIdx.x;
    if (e < N_EDGES) atomicAdd(&g_deg[dst[e]], 1);
}

// Phase A: per-block sums of degree chunks
__global__ void scanA_kernel() {
    __shared__ int sh[SCAN_CHUNK];
    int tid = threadIdx.x;
    int i = blockIdx.x * SCAN_CHUNK + tid;
    sh[tid] = (i < N_NODES) ? g_deg[i] : 0;
    __syncthreads();
#pragma unroll
    for (int off = SCAN_CHUNK / 2; off > 0; off >>= 1) {
        if (tid < off) sh[tid] += sh[tid + off];
        __syncthreads();
    }
    if (tid == 0) g_blk_sum[blockIdx.x] = sh[0];
}

// Phase B: single small block scans the 98 block sums (exclusive)
__global__ void scanB_kernel() {
    __shared__ int sh[128];
    int tid = threadIdx.x;
    int v = (tid < SCAN_BLOCKS) ? g_blk_sum[tid] : 0;
    sh[tid] = v;
    __syncthreads();
#pragma unroll
    for (int off = 1; off < 128; off <<= 1) {
        int t = (tid >= off) ? sh[tid - off] : 0;
        __syncthreads();
        sh[tid] += t;
        __syncthreads();
    }
    if (tid < SCAN_BLOCKS) g_blk_off[tid] = sh[tid] - v;  // exclusive
    if (tid == 0) g_row_ptr[N_NODES] = N_EDGES;
}

// Phase C: per-chunk exclusive scan + block offset -> row_ptr, cursor, inv_deg
__global__ void scanC_kernel() {
    __shared__ int sh[SCAN_CHUNK];
    int tid = threadIdx.x;
    int i = blockIdx.x * SCAN_CHUNK + tid;
    int d = (i < N_NODES) ? g_deg[i] : 0;
    sh[tid] = d;
    __syncthreads();
#pragma unroll
    for (int off = 1; off < SCAN_CHUNK; off <<= 1) {
        int t = (tid >= off) ? sh[tid - off] : 0;
        __syncthreads();
        sh[tid] += t;
        __syncthreads();
    }
    if (i < N_NODES) {
        int excl = g_blk_off[blockIdx.x] + sh[tid] - d;
        g_row_ptr[i] = excl;
        g_cursor[i] = excl;
        g_inv_deg[i] = 1.0f / (float)(d > 1 ? d : 1);
    }
}

__global__ void fill_csr_kernel(const int* __restrict__ src, const int* __restrict__ dst) {
    int e = blockIdx.x * blockDim.x + threadIdx.x;
    if (e < N_EDGES) {
        int idx = atomicAdd(&g_cursor[dst[e]], 1);
        g_csr_src[idx] = src[e];
    }
}

// ---------------- fused weight prep for all 3 layers ----------------
__global__ void prep_all_kernel(const float* __restrict__ Ws0, const float* __restrict__ Wn0,
                                const float* __restrict__ Ws1, const float* __restrict__ Wn1,
                                const float* __restrict__ Ws2, const float* __restrict__ Wn2) {
    int layer = blockIdx.y;
    int i = blockIdx.x * blockDim.x + threadIdx.x;
    const float* Ws;
    const float* Wn;
    __half* Bh;
    __half* Bl;
    int nreal, npad;
    if (layer == 0) { Ws = Ws0; Wn = Wn0; Bh = g_B0hi; Bl = g_B0lo; nreal = 128; npad = 128; }
    else if (layer == 1) { Ws = Ws1; Wn = Wn1; Bh = g_B1hi; Bl = g_B1lo; nreal = 128; npad = 128; }
    else { Ws = Ws2; Wn = Wn2; Bh = g_B2hi; Bl = g_B2lo; nreal = 47; npad = 48; }
    if (i >= npad * 256) return;
    int n = i / 256, k = i % 256;
    float w = 0.0f;
    if (n < nreal) w = (k < 128) ? Ws[k * nreal + n] : Wn[(k - 128) * nreal + n];
    unsigned short h, l;
    split2(w, h, l);
    Bh[i] = __ushort_as_half(h);
    Bl[i] = __ushort_as_half(l);
}

// ---------------- fp32 -> fp16 hi/lo split (features) ----------------
__global__ void split_kernel(const float* __restrict__ x,
                             __half* __restrict__ hi, __half* __restrict__ lo, int n) {
    int i = blockIdx.x * blockDim.x + threadIdx.x;
    if (i >= n) return;
    unsigned short h, l;
    split2(x[i], h, l);
    hi[i] = __ushort_as_half(h);
    lo[i] = __ushort_as_half(l);
}

// ---------------- mean aggregation over fp16 hi rows: one warp per node ----------------
__global__ void agg_kernel(const __half* __restrict__ hsrc) {
    int warp = (blockIdx.x * blockDim.x + threadIdx.x) >> 5;
    int lane = threadIdx.x & 31;
    if (warp >= N_NODES) return;
    int beg = g_row_ptr[warp];
    int end = g_row_ptr[warp + 1];
    float a0 = 0.f, a1 = 0.f, a2 = 0.f, a3 = 0.f;
    int e = beg;
    for (; e + 4 <= end; e += 4) {
        int u0 = __ldg(&g_csr_src[e]);
        int u1 = __ldg(&g_csr_src[e + 1]);
        int u2 = __ldg(&g_csr_src[e + 2]);
        int u3 = __ldg(&g_csr_src[e + 3]);
        uint2 v0 = __ldg((const uint2*)&hsrc[(long)u0 * D + lane * 4]);
        uint2 v1 = __ldg((const uint2*)&hsrc[(long)u1 * D + lane * 4]);
        uint2 v2 = __ldg((const uint2*)&hsrc[(long)u2 * D + lane * 4]);
        uint2 v3 = __ldg((const uint2*)&hsrc[(long)u3 * D + lane * 4]);
#pragma unroll
        for (int j = 0; j < 4; j++) {
            uint2 v = (j == 0) ? v0 : (j == 1) ? v1 : (j == 2) ? v2 : v3;
            float2 p0 = __half22float2(*(__half2*)&v.x);
            float2 p1 = __half22float2(*(__half2*)&v.y);
            a0 += p0.x; a1 += p0.y; a2 += p1.x; a3 += p1.y;
        }
    }
    for (; e < end; e++) {
        int u = __ldg(&g_csr_src[e]);
        uint2 v = __ldg((const uint2*)&hsrc[(long)u * D + lane * 4]);
        float2 p0 = __half22float2(*(__half2*)&v.x);
        float2 p1 = __half22float2(*(__half2*)&v.y);
        a0 += p0.x; a1 += p0.y; a2 += p1.x; a3 += p1.y;
    }
    float s = g_inv_deg[warp];
    float vals[4] = {a0 * s, a1 * s, a2 * s, a3 * s};
    unsigned short hs[4], ls[4];
#pragma unroll
    for (int j = 0; j < 4; j++) split2(vals[j], hs[j], ls[j]);
    long off = (long)warp * D + lane * 4;
    *(ushort4*)&g_agg_hi[off] = make_ushort4(hs[0], hs[1], hs[2], hs[3]);
    *(ushort4*)&g_agg_lo[off] = make_ushort4(ls[0], ls[1], ls[2], ls[3]);
}

// ---------------- HMMA fused GEMM: D[128,NOUT] = [x|agg](hi+lo) @ B(hi+lo)^T + b ----------------
// Error-split: acc = a_hi*b_hi + a_hi*b_lo + a_lo*b_hi
template <int NOUT, bool RELU, bool SPLIT, bool WF32>
__global__ void __launch_bounds__(256, 1) gemm_mma(
    const __half* __restrict__ x_hi, const __half* __restrict__ x_lo,
    const __half* __restrict__ Bhi_g, const __half* __restrict__ Blo_g,
    const float* __restrict__ bias, int nbias,
    float* __restrict__ out, int ostride,
    __half* __restrict__ o_hi, __half* __restrict__ o_lo) {
    constexpr int KS_B = 264;
    constexpr int KS_A = 136;
    constexpr int MT = (NOUT == 128) ? 2 : 1;
    constexpr int NT = (NOUT == 128) ? 8 : 6;

    extern __shared__ __half sm[];
    __half* sBhi = sm;
    __half* sBlo = sBhi + NOUT * KS_B;
    __half* sAhi = sBlo + NOUT * KS_B;
    __half* sAlo = sAhi + 128 * KS_A;
    float* sbias = (float*)(sAlo + 128 * KS_A);

    int tid = threadIdx.x;
    int wid = tid >> 5;
    int lane = tid & 31;
    int m0 = blockIdx.x * 128;

    int warpM = (NOUT == 128) ? (wid & 3) * 32 : wid * 16;
    int warpN = (NOUT == 128) ? (wid >> 2) * 64 : 0;

    for (int i = tid; i < NOUT * 32; i += 256) {
        int n = i >> 5;
        int k8 = (i & 31) << 3;
        *(uint4*)&sBhi[n * KS_B + k8] = *(const uint4*)&Bhi_g[n * 256 + k8];
        *(uint4*)&sBlo[n * KS_B + k8] = *(const uint4*)&Blo_g[n * 256 + k8];
    }
    if (tid < NOUT) sbias[tid] = (tid < nbias) ? bias[tid] : 0.0f;

    float acc[MT][NT][4];
#pragma unroll
    for (int mt = 0; mt < MT; mt++)
#pragma unroll
        for (int nt = 0; nt < NT; nt++)
#pragma unroll
            for (int j = 0; j < 4; j++) acc[mt][nt][j] = 0.0f;

    uint32_t uAhi = s2u(sAhi), uAlo = s2u(sAlo);
    uint32_t uBhi = s2u(sBhi), uBlo = s2u(sBlo);

    int g = lane >> 3;
    int rA = (g & 1) * 8 + (lane & 7);
    int kA = (g >> 1) * 8;
    int rB = lane & 7;
    int kB = ((lane >> 3) & 1) * 8;

#pragma unroll 1
    for (int c = 0; c < 2; c++) {
        const __half* shi = (c == 0) ? x_hi : g_agg_hi;
        const __half* slo = (c == 0) ? x_lo : g_agg_lo;
        __syncthreads();
        for (int i = tid; i < 128 * 16; i += 256) {
            int r = i >> 4;
            int k8 = (i & 15) << 3;
            int m = m0 + r;
            uint4 vh = make_uint4(0, 0, 0, 0), vl = make_uint4(0, 0, 0, 0);
            if (m < N_NODES) {
                vh = *(const uint4*)&shi[(long)m * 128 + k8];
                vl = *(const uint4*)&slo[(long)m * 128 + k8];
            }
            *(uint4*)&sAhi[r * KS_A + k8] = vh;
            *(uint4*)&sAlo[r * KS_A + k8] = vl;
        }
        __syncthreads();

#pragma unroll
        for (int kk = 0; kk < 128; kk += 16) {
            uint32_t ah[MT][4], al[MT][4];
#pragma unroll
            for (int mt = 0; mt < MT; mt++) {
                uint32_t off = (uint32_t)((warpM + mt * 16 + rA) * KS_A + kk + kA) * 2;
                ldsm_x4(ah[mt][0], ah[mt][1], ah[mt][2], ah[mt][3], uAhi + off);
                ldsm_x4(al[mt][0], al[mt][1], al[mt][2], al[mt][3], uAlo + off);
            }
            uint32_t bh[NT][2], bl[NT][2];
#pragma unroll
            for (int nt = 0; nt < NT; nt++) {
                uint32_t off = (uint32_t)((warpN + nt * 8 + rB) * KS_B + c * 128 + kk + kB) * 2;
                ldsm_x2(bh[nt][0], bh[nt][1], uBhi + off);
                ldsm_x2(bl[nt][0], bl[nt][1], uBlo + off);
            }
#pragma unroll
            for (int mt = 0; mt < MT; mt++)
#pragma unroll
                for (int nt = 0; nt < NT; nt++) {
                    mma_f16(acc[mt][nt], ah[mt], bh[nt]);
                    mma_f16(acc[mt][nt], ah[mt], bl[nt]);
                    mma_f16(acc[mt][nt], al[mt], bh[nt]);
                }
        }
    }

    // ---- epilogue ----
    int qr = lane >> 2;
    int qc = (lane & 3) * 2;
#pragma unroll
    for (int mt = 0; mt < MT; mt++) {
#pragma unroll
        for (int nt = 0; nt < NT; nt++) {
            int n = warpN + nt * 8 + qc;
            float bn0 = sbias[n], bn1 = sbias[n + 1];
#pragma unroll
            for (int half = 0; half < 2; half++) {
                int m = m0 + warpM + mt * 16 + qr + half * 8;
                if (m >= N_NODES) continue;
                float v0 = acc[mt][nt][half * 2 + 0] + bn0;
                float v1 = acc[mt][nt][half * 2 + 1] + bn1;
                if (RELU) { v0 = fmaxf(v0, 0.0f); v1 = fmaxf(v1, 0.0f); }
                if (NOUT == 128) {
                    if (WF32) *(float2*)&out[(long)m * ostride + n] = make_float2(v0, v1);
                    if (SPLIT) {
                        unsigned short h0, h1, l0, l1;
                        split2(v0, h0, l0);
                        split2(v1, h1, l1);
                        *(uint32_t*)&o_hi[(long)m * 128 + n] = (uint32_t)h0 | ((uint32_t)h1 << 16);
                        *(uint32_t*)&o_lo[(long)m * 128 + n] = (uint32_t)l0 | ((uint32_t)l1 << 16);
                    }
                } else {
                    if (n < N_CLS) out[(long)m * ostride + n] = v0;
                    if (n + 1 < N_CLS) out[(long)m * ostride + n + 1] = v1;
                }
            }
        }
    }
}

// ---------------- launch ----------------
extern "C" void kernel_launch(void* const* d_in, const int* in_sizes, int n_in,
                              void* d_out, int out_size) {
    const float* features = (const float*)d_in[0];
    const int*   src      = (const int*)d_in[1];
    const int*   dst      = (const int*)d_in[2];
    const float* Ws0 = (const float*)d_in[3];
    const float* Wn0 = (const float*)d_in[4];
    const float* b0  = (const float*)d_in[5];
    const float* Ws1 = (const float*)d_in[6];
    const float* Wn1 = (const float*)d_in[7];
    const float* b1  = (const float*)d_in[8];
    const float* Ws2 = (const float*)d_in[9];
    const float* Wn2 = (const float*)d_in[10];
    const float* b2  = (const float*)d_in[11];
    float* out = (float*)d_out;

    void* p;
    cudaGetSymbolAddress(&p, g_f_hi);  __half* f_hi = (__half*)p;
    cudaGetSymbolAddress(&p, g_f_lo);  __half* f_lo = (__half*)p;
    cudaGetSymbolAddress(&p, g_h1_hi); __half* h1_hi = (__half*)p;
    cudaGetSymbolAddress(&p, g_h1_lo); __half* h1_lo = (__half*)p;
    cudaGetSymbolAddress(&p, g_h2_hi); __half* h2_hi = (__half*)p;
    cudaGetSymbolAddress(&p, g_h2_lo); __half* h2_lo = (__half*)p;
    cudaGetSymbolAddress(&p, g_B0hi);  __half* B0h = (__half*)p;
    cudaGetSymbolAddress(&p, g_B0lo);  __half* B0l = (__half*)p;
    cudaGetSymbolAddress(&p, g_B1hi);  __half* B1h = (__half*)p;
    cudaGetSymbolAddress(&p, g_B1lo);  __half* B1l = (__half*)p;
    cudaGetSymbolAddress(&p, g_B2hi);  __half* B2h = (__half*)p;
    cudaGetSymbolAddress(&p, g_B2lo);  __half* B2l = (__half*)p;
    void* degp; cudaGetSymbolAddress(&degp, g_deg);

    const int SMEM128 = (2 * 128 * 264 + 2 * 128 * 136) * 2 + 512;  // 205,312
    const int SMEM48  = (2 * 48 * 264 + 2 * 128 * 136) * 2 + 512;   // 120,704
    cudaFuncSetAttribute(gemm_mma<128, true, true, false>,
                         cudaFuncAttributeMaxDynamicSharedMemorySize, SMEM128);
    cudaFuncSetAttribute(gemm_mma<48, false, false, true>,
                         cudaFuncAttributeMaxDynamicSharedMemorySize, SMEM48);

    // Fork: CSR chain on main stream, weight-prep + feature-split on s2.
    cudaStream_t s2;
    cudaStreamCreateWithFlags(&s2, cudaStreamNonBlocking);
    cudaEvent_t e_fork, e_join;
    cudaEventCreateWithFlags(&e_fork, cudaEventDisableTiming);
    cudaEventCreateWithFlags(&e_join, cudaEventDisableTiming);

    cudaEventRecord(e_fork, 0);
    cudaStreamWaitEvent(s2, e_fork, 0);

    // s2: prep + split
    prep_all_kernel<<<dim3(128, 3), 256, 0, s2>>>(Ws0, Wn0, Ws1, Wn1, Ws2, Wn2);
    split_kernel<<<(N_NODES * D + 255) / 256, 256, 0, s2>>>(features, f_hi, f_lo, N_NODES * D);
    cudaEventRecord(e_join, s2);

    // main: CSR build (multi-block scan replaces the 102us single-block scan)
    cudaMemsetAsync(degp, 0, N_NODES * sizeof(int));
    count_deg_kernel<<<(N_EDGES + 255) / 256, 256>>>(dst);
    scanA_kernel<<<SCAN_BLOCKS, SCAN_CHUNK>>>();
    scanB_kernel<<<1, 128>>>();
    scanC_kernel<<<SCAN_BLOCKS, SCAN_CHUNK>>>();
    fill_csr_kernel<<<(N_EDGES + 255) / 256, 256>>>(src, dst);

    cudaStreamWaitEvent(0, e_join, 0);

    const int AGG_BLOCKS = (N_NODES * 32 + 255) / 256;
    const int GEMM_BLOCKS = (N_NODES + 127) / 128;  // 391

    // Layer 0
    agg_kernel<<<AGG_BLOCKS, 256>>>(f_hi);
    gemm_mma<128, true, true, false><<<GEMM_BLOCKS, 256, SMEM128>>>(
        f_hi, f_lo, B0h, B0l, b0, 128, nullptr, 128, h1_hi, h1_lo);

    // Layer 1
    agg_kernel<<<AGG_BLOCKS, 256>>>(h1_hi);
    gemm_mma<128, true, true, false><<<GEMM_BLOCKS, 256, SMEM128>>>(
        h1_hi, h1_lo, B1h, B1l, b1, 128, nullptr, 128, h2_hi, h2_lo);

    // Layer 2 (47 classes, no relu)
    agg_kernel<<<AGG_BLOCKS, 256>>>(h2_hi);
    gemm_mma<48, false, false, true><<<GEMM_BLOCKS, 256, SMEM48>>>(
        h2_hi, h2_lo, B2h, B2l, b2, 47, out, 47, nullptr, nullptr);
}